// round 14
// baseline (speedup 1.0000x reference)
#include <cuda_runtime.h>
#include <cstdint>
#include <math.h>

#define B_  32
#define T_  512
#define S_  64
#define D_  768
#define C_  8
#define NW_ 1536   // packed [Wqk | Wv] width

// ---------------- scratch (static device globals; allocation-free) ----------
__device__ float g_x  [B_*T_*D_];
__device__ float g_QV [B_*T_*NW_];   // cols 0..767 = Qk, 768..1535 = Vt
__device__ float g_M0 [B_*S_*D_];
__device__ float g_M1 [B_*S_*D_];
__device__ float g_Mt0[B_*S_*D_];    // tf32 shadow
__device__ float g_Mt1[B_*S_*D_];
__device__ float g_W  [B_*T_*S_];
__device__ float g_Wp [D_*NW_];
__device__ float g_gWr[D_*D_];
__device__ float g_cwp[B_*32*S_];
__device__ float g_valid[B_];

// ---------------- helpers ----------------------------------------------------
__device__ __forceinline__ float to_tf32(float f) {
    unsigned int u;
    asm("cvt.rna.tf32.f32 %0, %1;" : "=r"(u) : "f"(f));
    return __uint_as_float(u);
}

__device__ __forceinline__ void mma_tf32(float& c0, float& c1, float& c2, float& c3,
                                         float a0, float a1, float a2, float a3,
                                         float b0, float b1) {
    asm("mma.sync.aligned.m16n8k8.row.col.f32.tf32.tf32.f32 "
        "{%0,%1,%2,%3}, {%4,%5,%6,%7}, {%8,%9}, {%0,%1,%2,%3};"
        : "+f"(c0), "+f"(c1), "+f"(c2), "+f"(c3)
        : "r"(__float_as_uint(a0)), "r"(__float_as_uint(a1)),
          "r"(__float_as_uint(a2)), "r"(__float_as_uint(a3)),
          "r"(__float_as_uint(b0)), "r"(__float_as_uint(b1)));
}

__device__ __forceinline__ void cp_async16(float* dst, const float* src) {
    unsigned u = (unsigned)__cvta_generic_to_shared(dst);
    asm volatile("cp.async.cg.shared.global [%0], [%1], 16;" :: "r"(u), "l"(src));
}
#define CP_COMMIT() asm volatile("cp.async.commit_group;")
#define CP_WAIT0()  asm volatile("cp.async.wait_group 0;")
template<int N> __device__ __forceinline__ void cp_wait() {
    asm volatile("cp.async.wait_group %0;" :: "n"(N));
}

// ---------------- small kernels ---------------------------------------------
__global__ void k_valid(const int* __restrict__ mask) {
    __shared__ int sh[512];
    int b = blockIdx.x, t = threadIdx.x;
    sh[t] = (mask[b*T_ + t] > 0) ? 1 : 0;
    __syncthreads();
    for (int o = 256; o > 0; o >>= 1) {
        if (t < o) sh[t] += sh[t + o];
        __syncthreads();
    }
    if (t == 0) g_valid[b] = (float)sh[0];
}

__global__ void k_embed(const int* __restrict__ ids,
                        const float* __restrict__ tok,
                        const float* __restrict__ pos) {
    int bt = blockIdx.x;
    int t  = bt % T_;
    long id = ids[bt];
    const float4* te = (const float4*)(tok + id * (long)D_);
    const float4* pe = (const float4*)(pos + (long)t * D_);
    float4* xo = (float4*)(g_x + (long)bt * D_);
    int i = threadIdx.x;
    float4 a = te[i], p4 = pe[i];
    a.x = to_tf32(a.x + p4.x); a.y = to_tf32(a.y + p4.y);
    a.z = to_tf32(a.z + p4.z); a.w = to_tf32(a.w + p4.w);
    xo[i] = a;
}

__global__ void k_minit(const float* __restrict__ mem) {
    int i = blockIdx.x * blockDim.x + threadIdx.x;
    if (i < B_*S_*D_) {
        float v = mem[i % (S_*D_)];
        g_M0[i]  = v;
        g_Mt0[i] = to_tf32(v);
    }
}

// pack gate_W (round) and Wv (into g_Wp right half) in one kernel
__global__ void k_prep(const float* __restrict__ gW, const float* __restrict__ Wv) {
    int i = blockIdx.x * blockDim.x + threadIdx.x;
    if (i >= D_*D_) return;
    g_gWr[i] = to_tf32(gW[i]);
    int k = i / D_, j = i % D_;
    g_Wp[(size_t)k*NW_ + D_ + j] = to_tf32(Wv[i]);
}

// ---------------- generic tf32 GEMM, multistage cp.async ---------------------
// MODE 0 = NN, MODE 1 = NT
template<int BM, int BN, int WM, int WN, int MODE, bool CVT_A, bool CVT_B, int NST>
__global__ void __launch_bounds__((BM/WM)*(BN/WN)*32)
gemm_tc(const float* __restrict__ Ag, const float* __restrict__ Bg, float* __restrict__ Cg,
        int M, int N, int K, int lda, int ldb, int ldc)
{
    constexpr int BK = 32;
    constexpr int WARPS   = (BM/WM)*(BN/WN);
    constexpr int THREADS = WARPS*32;
    constexpr int MA = WM/16;
    constexpr int NA = WN/8;
    constexpr int ALD = 36;
    constexpr int AE  = BM*ALD;
    constexpr int BLD = (MODE==1) ? 36 : (BN+8);
    constexpr int BE  = ((MODE==1) ? BN : BK)*BLD;

    extern __shared__ float smbuf[];
    float* Abuf = smbuf;
    float* Bbuf = smbuf + NST*AE;

    const float* A = Ag;
    const float* B = Bg;
    float*       C = Cg;

    const int tid    = threadIdx.x;
    const int warpId = tid >> 5;
    const int lane   = tid & 31;
    const int g      = lane >> 2;
    const int tig    = lane & 3;
    const int warp_m = (warpId % (BM/WM)) * WM;
    const int warp_n = (warpId / (BM/WM)) * WN;
    const int rowBase = blockIdx.y * BM;
    const int colBase = blockIdx.x * BN;

    float acc[MA][NA][4];
#pragma unroll
    for (int i = 0; i < MA; i++)
#pragma unroll
        for (int j = 0; j < NA; j++) {
            acc[i][j][0]=0.f; acc[i][j][1]=0.f; acc[i][j][2]=0.f; acc[i][j][3]=0.f;
        }

    auto load_tile = [&](int kt, int s) {
        const int k0 = kt * BK;
        float* As = Abuf + s*AE;
        float* Bs = Bbuf + s*BE;
#pragma unroll
        for (int idx = tid; idx < BM*8; idx += THREADS) {
            int r = idx >> 3, c = idx & 7;
            cp_async16(As + r*ALD + 4*c, A + (long long)(rowBase + r)*lda + k0 + 4*c);
        }
        if (MODE == 1) {
#pragma unroll
            for (int idx = tid; idx < BN*8; idx += THREADS) {
                int r = idx >> 3, c = idx & 7;
                cp_async16(Bs + r*BLD + 4*c, B + (long long)(colBase + r)*ldb + k0 + 4*c);
            }
        } else {
#pragma unroll
            for (int idx = tid; idx < BK*(BN/4); idx += THREADS) {
                int r = idx / (BN/4), c = idx % (BN/4);
                cp_async16(Bs + r*BLD + 4*c, B + (long long)(k0 + r)*ldb + colBase + 4*c);
            }
        }
    };

    const int KT = K / BK;
#pragma unroll
    for (int s = 0; s < NST-1; s++) {
        if (s < KT) load_tile(s, s);
        CP_COMMIT();
    }

    for (int kt = 0; kt < KT; kt++) {
        const int pf = kt + NST - 1;
        if (pf < KT) load_tile(pf, pf % NST);
        CP_COMMIT();
        cp_wait<NST-2>();
        __syncthreads();

        const int cur = kt % NST;
        const float* As = Abuf + cur*AE;
        const float* Bs = Bbuf + cur*BE;

#pragma unroll
        for (int ks = 0; ks < 4; ks++) {
            const int kk = 8*ks;
            float a[MA][4], bf[NA][2];
#pragma unroll
            for (int ma = 0; ma < MA; ma++) {
                int mb = warp_m + 16*ma + g;
                const float* p0 = As + mb*ALD;
                const float* p1 = As + (mb+8)*ALD;
                a[ma][0] = p0[kk+tig];   a[ma][1] = p1[kk+tig];
                a[ma][2] = p0[kk+tig+4]; a[ma][3] = p1[kk+tig+4];
            }
            if (CVT_A) {
#pragma unroll
                for (int ma = 0; ma < MA; ma++)
#pragma unroll
                    for (int j = 0; j < 4; j++) a[ma][j] = to_tf32(a[ma][j]);
            }
            if (MODE == 1) {
#pragma unroll
                for (int na = 0; na < NA; na++) {
                    const float* p = Bs + (warp_n + 8*na + g)*BLD;
                    bf[na][0] = p[kk+tig]; bf[na][1] = p[kk+tig+4];
                }
            } else {
                const float* q0 = Bs + (kk + tig    )*BLD;
                const float* q1 = Bs + (kk + tig + 4)*BLD;
#pragma unroll
                for (int na = 0; na < NA; na++) {
                    int nb = warp_n + 8*na + g;
                    bf[na][0] = q0[nb]; bf[na][1] = q1[nb];
                }
            }
            if (CVT_B) {
#pragma unroll
                for (int na = 0; na < NA; na++) {
                    bf[na][0] = to_tf32(bf[na][0]);
                    bf[na][1] = to_tf32(bf[na][1]);
                }
            }
#pragma unroll
            for (int ma = 0; ma < MA; ma++)
#pragma unroll
                for (int na = 0; na < NA; na++)
                    mma_tf32(acc[ma][na][0], acc[ma][na][1], acc[ma][na][2], acc[ma][na][3],
                             a[ma][0], a[ma][1], a[ma][2], a[ma][3],
                             bf[na][0], bf[na][1]);
        }
        __syncthreads();
    }

#pragma unroll
    for (int ma = 0; ma < MA; ma++) {
        int r0 = rowBase + warp_m + 16*ma + g;
        int r1 = r0 + 8;
#pragma unroll
        for (int na = 0; na < NA; na++) {
            int cc = colBase + warp_n + 8*na + 2*tig;
            *(float2*)(C + (long long)r0*ldc + cc) =
                make_float2(to_tf32(acc[ma][na][0]), to_tf32(acc[ma][na][1]));
            *(float2*)(C + (long long)r1*ldc + cc) =
                make_float2(to_tf32(acc[ma][na][2]), to_tf32(acc[ma][na][3]));
        }
    }
}

// ---------------- fused scores+softmax (+optional colsum partials) -----------
// B operand (M slots) comes pre-rounded to tf32 (g_Mt*) -> no cvt in inner loop.
#define SCO_NST 4
__global__ void __launch_bounds__(128)
k_score_softmax(const float* __restrict__ Qk, const float* __restrict__ Mtf,
                float* __restrict__ Wout, const int* __restrict__ mask,
                float* __restrict__ csum)   // non-null => colsum partials, no W store
{
    constexpr int AE = 64*36;
    extern __shared__ float smbuf[];
    float* Abuf = smbuf;
    float* Bbuf = smbuf + SCO_NST*AE;

    const int b = blockIdx.z;
    const int rowBase = blockIdx.y * 64;
    const float* A  = Qk  + (long long)b*T_*NW_;
    const float* Bm = Mtf + (long long)b*S_*D_;

    const int tid  = threadIdx.x;
    const int w    = tid >> 5;
    const int lane = tid & 31;
    const int g    = lane >> 2;
    const int tig  = lane & 3;

    float acc[8][4];
#pragma unroll
    for (int j = 0; j < 8; j++) { acc[j][0]=0.f; acc[j][1]=0.f; acc[j][2]=0.f; acc[j][3]=0.f; }

    auto load_tile = [&](int kt, int s) {
        const int k0 = kt * 32;
        float* As = Abuf + s*AE;
        float* Bs = Bbuf + s*AE;
#pragma unroll
        for (int idx = tid; idx < 512; idx += 128) {
            int r = idx >> 3, c = idx & 7;
            cp_async16(As + r*36 + 4*c, A + (long long)(rowBase + r)*NW_ + k0 + 4*c);
        }
#pragma unroll
        for (int idx = tid; idx < 512; idx += 128) {
            int r = idx >> 3, c = idx & 7;
            cp_async16(Bs + r*36 + 4*c, Bm + (long long)r*D_ + k0 + 4*c);
        }
    };

#pragma unroll
    for (int s = 0; s < SCO_NST-1; s++) { load_tile(s, s); CP_COMMIT(); }

    for (int kt = 0; kt < 24; kt++) {
        const int pf = kt + SCO_NST - 1;
        if (pf < 24) load_tile(pf, pf % SCO_NST);
        CP_COMMIT();
        cp_wait<SCO_NST-2>();
        __syncthreads();
        const int cur = kt % SCO_NST;
        const float* As = Abuf + cur*AE;
        const float* Bs = Bbuf + cur*AE;
#pragma unroll
        for (int ks = 0; ks < 4; ks++) {
            const int kk = 8*ks;
            int mb = 16*w + g;
            const float* p0 = As + mb*36;
            const float* p1 = As + (mb+8)*36;
            float a0 = p0[kk+tig],   a1 = p1[kk+tig];
            float a2 = p0[kk+tig+4], a3 = p1[kk+tig+4];
            float bf[8][2];
#pragma unroll
            for (int na = 0; na < 8; na++) {
                const float* p = Bs + (8*na + g)*36;
                bf[na][0] = p[kk+tig]; bf[na][1] = p[kk+tig+4];
            }
#pragma unroll
            for (int na = 0; na < 8; na++)
                mma_tf32(acc[na][0], acc[na][1], acc[na][2], acc[na][3],
                         a0, a1, a2, a3, bf[na][0], bf[na][1]);
        }
        __syncthreads();
    }

    // softmax epilogue: warp owns full rows t0 = rowBase+16w+g and t1 = t0+8.
    const float scale = 0.03608439182435161f;
    float mx0 = -1e30f, mx1 = -1e30f;
#pragma unroll
    for (int na = 0; na < 8; na++) {
#pragma unroll
        for (int j = 0; j < 4; j++) {
            float v = fminf(fmaxf(acc[na][j]*scale, -20.f), 20.f);
            acc[na][j] = v;
            if (j < 2) mx0 = fmaxf(mx0, v); else mx1 = fmaxf(mx1, v);
        }
    }
    mx0 = fmaxf(mx0, __shfl_xor_sync(0xffffffffu, mx0, 1));
    mx0 = fmaxf(mx0, __shfl_xor_sync(0xffffffffu, mx0, 2));
    mx1 = fmaxf(mx1, __shfl_xor_sync(0xffffffffu, mx1, 1));
    mx1 = fmaxf(mx1, __shfl_xor_sync(0xffffffffu, mx1, 2));
    float sm0 = 0.f, sm1 = 0.f;
#pragma unroll
    for (int na = 0; na < 8; na++) {
        acc[na][0] = expf(acc[na][0] - mx0); sm0 += acc[na][0];
        acc[na][1] = expf(acc[na][1] - mx0); sm0 += acc[na][1];
        acc[na][2] = expf(acc[na][2] - mx1); sm1 += acc[na][2];
        acc[na][3] = expf(acc[na][3] - mx1); sm1 += acc[na][3];
    }
    sm0 += __shfl_xor_sync(0xffffffffu, sm0, 1);
    sm0 += __shfl_xor_sync(0xffffffffu, sm0, 2);
    sm1 += __shfl_xor_sync(0xffffffffu, sm1, 1);
    sm1 += __shfl_xor_sync(0xffffffffu, sm1, 2);
    const int t0 = rowBase + 16*w + g;
    const int t1 = t0 + 8;
    const int m0 = mask[b*T_ + t0] > 0;
    const int m1 = mask[b*T_ + t1] > 0;

    if (csum) {
        float c0 = m0 ? (1.f / sm0) : 0.f;
        float c1 = m1 ? (1.f / sm1) : 0.f;
        float part[8][2];
#pragma unroll
        for (int na = 0; na < 8; na++) {
            part[na][0] = acc[na][0]*c0 + acc[na][2]*c1;
            part[na][1] = acc[na][1]*c0 + acc[na][3]*c1;
        }
#pragma unroll
        for (int o = 4; o < 32; o <<= 1) {
#pragma unroll
            for (int na = 0; na < 8; na++) {
                part[na][0] += __shfl_xor_sync(0xffffffffu, part[na][0], o);
                part[na][1] += __shfl_xor_sync(0xffffffffu, part[na][1], o);
            }
        }
        if (g == 0) {
            float* dst = csum + ((size_t)b*32 + blockIdx.y*4 + w) * S_;
#pragma unroll
            for (int na = 0; na < 8; na++) {
                dst[8*na + 2*tig    ] = part[na][0];
                dst[8*na + 2*tig + 1] = part[na][1];
            }
        }
    } else {
        float vf  = g_valid[b];
        float mf0 = (vf > 0.f) ? (m0 ? 1.f : 0.f) : 1.f;
        float mf1 = (vf > 0.f) ? (m1 ? 1.f : 0.f) : 1.f;
        float i0 = mf0 / sm0, i1 = mf1 / sm1;
        float* r0 = Wout + ((size_t)b*T_ + t0)*S_;
        float* r1 = Wout + ((size_t)b*T_ + t1)*S_;
#pragma unroll
        for (int na = 0; na < 8; na++) {
            int cc = 8*na + 2*tig;
            *(float2*)(r0 + cc) = make_float2(to_tf32(acc[na][0]*i0), to_tf32(acc[na][1]*i0));
            *(float2*)(r1 + cc) = make_float2(to_tf32(acc[na][2]*i1), to_tf32(acc[na][3]*i1));
        }
    }
}

// ---------------- fused gate + write + memory update (3-stage) ---------------
// phase1 A = tf32 shadow of M (no cvt); epilogue reads fp32 M, writes fp32+tf32.
#define GW_NST 3
__global__ void __launch_bounds__(256)
k_gatewrite(const float* __restrict__ Mc, const float* __restrict__ Mtc,
            const float* __restrict__ gWr,
            const float* __restrict__ Wt, const float* __restrict__ Vtq,
            const float* __restrict__ gbp,
            float* __restrict__ Mn, float* __restrict__ Mtn)
{
    constexpr int AE = 2304;           // phase1: 64*36 ; phase2: 32*72
    constexpr int BE = 32*136;         // 4352
    extern __shared__ float smbuf[];
    float* Abuf = smbuf;
    float* Bbuf = smbuf + GW_NST*AE;

    const int b = blockIdx.z;
    const int colBase = blockIdx.x * 128;
    const float* Mp  = Mc  + (long long)b*S_*D_;
    const float* Mtp = Mtc + (long long)b*S_*D_;
    const float* Wp  = Wt  + (long long)b*T_*S_;
    const float* Vp  = Vtq + (long long)b*T_*NW_ + D_;

    const int tid  = threadIdx.x;
    const int wId  = tid >> 5;
    const int lane = tid & 31;
    const int g    = lane >> 2;
    const int tig  = lane & 3;
    const int warp_m = (wId & 1) * 32;
    const int warp_n = (wId >> 1) * 32;

    float accG[2][4][4], accW[2][4][4];
#pragma unroll
    for (int i = 0; i < 2; i++)
#pragma unroll
        for (int j = 0; j < 4; j++)
#pragma unroll
            for (int k = 0; k < 4; k++) { accG[i][j][k] = 0.f; accW[i][j][k] = 0.f; }

    // ---- phase 1: gate = Mt @ gWr, K = 768 ----
    auto loadG = [&](int kt, int s) {
        const int k0 = kt * 32;
        float* As = Abuf + s*AE;
        float* Bs = Bbuf + s*BE;
#pragma unroll
        for (int idx = tid; idx < 512; idx += 256) {
            int r = idx >> 3, c = idx & 7;
            cp_async16(As + r*36 + 4*c, Mtp + (long long)r*D_ + k0 + 4*c);
        }
#pragma unroll
        for (int idx = tid; idx < 1024; idx += 256) {
            int r = idx >> 5, c = idx & 31;
            cp_async16(Bs + r*136 + 4*c, gWr + (long long)(k0 + r)*D_ + colBase + 4*c);
        }
    };
#pragma unroll
    for (int s = 0; s < GW_NST-1; s++) { loadG(s, s); CP_COMMIT(); }
    for (int kt = 0; kt < 24; kt++) {
        const int pf = kt + GW_NST - 1;
        if (pf < 24) loadG(pf, pf % GW_NST);
        CP_COMMIT();
        cp_wait<GW_NST-2>();
        __syncthreads();
        const int cur = kt % GW_NST;
        const float* As = Abuf + cur*AE;
        const float* Bs = Bbuf + cur*BE;
#pragma unroll
        for (int ks = 0; ks < 4; ks++) {
            const int kk = 8*ks;
            float a[2][4], bf[4][2];
#pragma unroll
            for (int ma = 0; ma < 2; ma++) {
                int mb = warp_m + 16*ma + g;
                const float* p0 = As + mb*36;
                const float* p1 = As + (mb+8)*36;
                a[ma][0] = p0[kk+tig];   a[ma][1] = p1[kk+tig];
                a[ma][2] = p0[kk+tig+4]; a[ma][3] = p1[kk+tig+4];
            }
            const float* q0 = Bs + (kk + tig    )*136;
            const float* q1 = Bs + (kk + tig + 4)*136;
#pragma unroll
            for (int na = 0; na < 4; na++) {
                int nb = warp_n + 8*na + g;
                bf[na][0] = q0[nb]; bf[na][1] = q1[nb];
            }
#pragma unroll
            for (int ma = 0; ma < 2; ma++)
#pragma unroll
                for (int na = 0; na < 4; na++)
                    mma_tf32(accG[ma][na][0], accG[ma][na][1], accG[ma][na][2], accG[ma][na][3],
                             a[ma][0], a[ma][1], a[ma][2], a[ma][3],
                             bf[na][0], bf[na][1]);
        }
        __syncthreads();
    }
    CP_WAIT0();
    __syncthreads();

    // ---- phase 2: write = W^T @ Vt, K = 512 ----
    auto loadW = [&](int kt, int s) {
        const int k0 = kt * 32;
        float* As = Abuf + s*AE;
        float* Bs = Bbuf + s*BE;
#pragma unroll
        for (int idx = tid; idx < 512; idx += 256) {
            int r = idx >> 4, c = idx & 15;
            cp_async16(As + r*72 + 4*c, Wp + (long long)(k0 + r)*S_ + 4*c);
        }
#pragma unroll
        for (int idx = tid; idx < 1024; idx += 256) {
            int r = idx >> 5, c = idx & 31;
            cp_async16(Bs + r*136 + 4*c, Vp + (long long)(k0 + r)*NW_ + colBase + 4*c);
        }
    };
#pragma unroll
    for (int s = 0; s < GW_NST-1; s++) { loadW(s, s); CP_COMMIT(); }
    for (int kt = 0; kt < 16; kt++) {
        const int pf = kt + GW_NST - 1;
        if (pf < 16) loadW(pf, pf % GW_NST);
        CP_COMMIT();
        cp_wait<GW_NST-2>();
        __syncthreads();
        const int cur = kt % GW_NST;
        const float* As = Abuf + cur*AE;
        const float* Bs = Bbuf + cur*BE;
#pragma unroll
        for (int ks = 0; ks < 4; ks++) {
            const int kk = 8*ks;
            float a[2][4], bf[4][2];
            const float* r0 = As + (kk + tig    )*72;
            const float* r1 = As + (kk + tig + 4)*72;
#pragma unroll
            for (int ma = 0; ma < 2; ma++) {
                int mb = warp_m + 16*ma + g;
                a[ma][0] = r0[mb]; a[ma][1] = r0[mb+8];
                a[ma][2] = r1[mb]; a[ma][3] = r1[mb+8];
            }
            const float* q0 = Bs + (kk + tig    )*136;
            const float* q1 = Bs + (kk + tig + 4)*136;
#pragma unroll
            for (int na = 0; na < 4; na++) {
                int nb = warp_n + 8*na + g;
                bf[na][0] = q0[nb]; bf[na][1] = q1[nb];
            }
#pragma unroll
            for (int ma = 0; ma < 2; ma++)
#pragma unroll
                for (int na = 0; na < 4; na++)
                    mma_tf32(accW[ma][na][0], accW[ma][na][1], accW[ma][na][2], accW[ma][na][3],
                             a[ma][0], a[ma][1], a[ma][2], a[ma][3],
                             bf[na][0], bf[na][1]);
        }
        __syncthreads();
    }

    // ---- epilogue: M update (fp32 state + tf32 shadow) ----
    float* Mo  = Mn  + (long long)b*S_*D_;
    float* Mto = Mtn + (long long)b*S_*D_;
#pragma unroll
    for (int ma = 0; ma < 2; ma++) {
        int s0 = warp_m + 16*ma + g;
        int s1 = s0 + 8;
#pragma unroll
        for (int na = 0; na < 4; na++) {
            int cc = colBase + warp_n + 8*na + 2*tig;
            float2 gb2 = *(const float2*)(gbp + cc);
#pragma unroll
            for (int rr = 0; rr < 2; rr++) {
                int row = rr ? s1 : s0;
                float gx = accG[ma][na][2*rr]   + gb2.x;
                float gy = accG[ma][na][2*rr+1] + gb2.y;
                float sx = 1.f / (1.f + expf(-gx));
                float sy = 1.f / (1.f + expf(-gy));
                float2 mo = *(const float2*)(Mp + (long long)row*D_ + cc);
                float nx = fminf(fmaxf(0.9f*mo.x + 0.1f*sx*accW[ma][na][2*rr],   -50.f), 50.f);
                float ny = fminf(fmaxf(0.9f*mo.y + 0.1f*sy*accW[ma][na][2*rr+1], -50.f), 50.f);
                *(float2*)(Mo  + (long long)row*D_ + cc) = make_float2(nx, ny);
                *(float2*)(Mto + (long long)row*D_ + cc) =
                    make_float2(to_tf32(nx), to_tf32(ny));
            }
        }
    }
}

// ---------------- pooled; LayerNorm; logits ----------------------------------
__global__ void k_final(const float* __restrict__ ln_g, const float* __restrict__ ln_b,
                        const float* __restrict__ cls_W, const float* __restrict__ cls_b,
                        float* __restrict__ out)
{
    __shared__ float cw[S_];
    __shared__ float p[D_];
    __shared__ float red[256];
    int b = blockIdx.x, tid = threadIdx.x;
    if (tid < S_) {
        float a = 0.f;
        const float* cp = g_cwp + (size_t)b*32*S_ + tid;
#pragma unroll
        for (int i = 0; i < 32; i++) a += cp[i*S_];
        cw[tid] = a;
    }
    __syncthreads();
    float invn = 1.f / fmaxf(g_valid[b], 1.f);
    for (int d = tid; d < D_; d += 256) {
        float acc = 0.f;
        const float* Mb = g_M0 + (size_t)b*S_*D_ + d;
#pragma unroll 8
        for (int s = 0; s < S_; s++) acc += cw[s] * Mb[s*D_];
        p[d] = acc * invn;
    }
    __syncthreads();
    float ls = 0.f;
    for (int d = tid; d < D_; d += 256) ls += p[d];
    red[tid] = ls; __syncthreads();
    for (int o = 128; o > 0; o >>= 1) { if (tid < o) red[tid] += red[tid + o]; __syncthreads(); }
    float mu = red[0] / D_;
    __syncthreads();
    float lv = 0.f;
    for (int d = tid; d < D_; d += 256) { float z = p[d] - mu; lv += z*z; }
    red[tid] = lv; __syncthreads();
    for (int o = 128; o > 0; o >>= 1) { if (tid < o) red[tid] += red[tid + o]; __syncthreads(); }
    float rs = rsqrtf(red[0] / D_ + 1e-5f);
    __syncthreads();
    for (int d = tid; d < D_; d += 256)
        p[d] = (p[d] - mu) * rs * ln_g[d] + ln_b[d];
    __syncthreads();
    int w = tid >> 5, lane = tid & 31;
    float acc = 0.f;
    for (int d = lane; d < D_; d += 32) acc += p[d] * cls_W[d*C_ + w];
#pragma unroll
    for (int o = 16; o > 0; o >>= 1) acc += __shfl_down_sync(0xffffffffu, acc, o);
    if (lane == 0) {
        float v = acc + cls_b[w];
        if (!isfinite(v)) v = 0.f;
        out[b*C_ + w] = v;
    }
}

// ---------------- launch -----------------------------------------------------
extern "C" void kernel_launch(void* const* d_in, const int* in_sizes, int n_in,
                              void* d_out, int out_size)
{
    const int*   ids  = (const int*)  d_in[0];
    const int*   mask = (const int*)  d_in[1];
    const float* tok  = (const float*)d_in[2];
    const float* pos  = (const float*)d_in[3];
    const float* Wq   = (const float*)d_in[4];
    const float* Wk   = (const float*)d_in[5];
    const float* Wv   = (const float*)d_in[6];
    const float* gW   = (const float*)d_in[7];
    const float* gb   = (const float*)d_in[8];
    const float* lng  = (const float*)d_in[9];
    const float* lnb  = (const float*)d_in[10];
    const float* cW   = (const float*)d_in[11];
    const float* cb   = (const float*)d_in[12];
    const float* mem  = (const float*)d_in[13];
    float* out = (float*)d_out;

    float *px, *pQV, *pM0, *pM1, *pMt0, *pMt1, *pW, *pWp, *pgWr, *pcwp;
    cudaGetSymbolAddress((void**)&px,   g_x);
    cudaGetSymbolAddress((void**)&pQV,  g_QV);
    cudaGetSymbolAddress((void**)&pM0,  g_M0);
    cudaGetSymbolAddress((void**)&pM1,  g_M1);
    cudaGetSymbolAddress((void**)&pMt0, g_Mt0);
    cudaGetSymbolAddress((void**)&pMt1, g_Mt1);
    cudaGetSymbolAddress((void**)&pW,   g_W);
    cudaGetSymbolAddress((void**)&pWp,  g_Wp);
    cudaGetSymbolAddress((void**)&pgWr, g_gWr);
    cudaGetSymbolAddress((void**)&pcwp, g_cwp);

    auto kWqk = gemm_tc<128,128,64,32, 1, true , true , 3>;  // Wqk = Wq @ Wk^T
    auto kBig = gemm_tc<128,128,64,64, 0, false, false, 3>;  // QV = x @ [Wqk|Wv], 4 warps 64x64

    const int SM_WQK = 3*(128*36 + 128*36)*4;  // 110592
    const int SM_BIG = 3*(128*36 +  32*136)*4; // 107520
    const int SM_SCO = SCO_NST*2*(64*36)*4;    // 73728
    const int SM_GW  = GW_NST*(2304 + 4352)*4; // 79872

    cudaFuncSetAttribute(kWqk, cudaFuncAttributeMaxDynamicSharedMemorySize, SM_WQK);
    cudaFuncSetAttribute(kBig, cudaFuncAttributeMaxDynamicSharedMemorySize, SM_BIG);
    cudaFuncSetAttribute(k_score_softmax, cudaFuncAttributeMaxDynamicSharedMemorySize, SM_SCO);
    cudaFuncSetAttribute(k_gatewrite,     cudaFuncAttributeMaxDynamicSharedMemorySize, SM_GW);

    k_valid<<<B_, 512>>>(mask);
    k_embed<<<B_*T_, 192>>>(ids, tok, pos);
    kWqk<<<dim3(D_/128, D_/128, 1), 256, SM_WQK>>>(Wq, Wk, pWp, D_, D_, D_, D_, D_, NW_);
    k_prep<<<(D_*D_ + 255)/256, 256>>>(gW, Wv);
    kBig<<<dim3(NW_/128, (B_*T_)/128, 1), 128, SM_BIG>>>(px, pWp, pQV, B_*T_, NW_, D_, D_, NW_, NW_);
    k_minit<<<(B_*S_*D_ + 255)/256, 256>>>(mem);

    float* Mbuf [2] = {pM0,  pM1};
    float* Mtbuf[2] = {pMt0, pMt1};
    for (int step = 0; step < 4; step++) {
        const float* Mc  = Mbuf [step & 1];
        const float* Mtc = Mtbuf[step & 1];
        float*       Mn  = Mbuf [(step & 1) ^ 1];
        float*       Mtn = Mtbuf[(step & 1) ^ 1];
        k_score_softmax<<<dim3(1, T_/64, B_), 128, SM_SCO>>>(pQV, Mtc, pW, mask, nullptr);
        k_gatewrite<<<dim3(D_/128, 1, B_), 256, SM_GW>>>(Mc, Mtc, pgWr, pW, pQV, gb, Mn, Mtn);
    }
    // after 4 steps state is back in M0/Mt0; final read -> colsum partials only
    k_score_softmax<<<dim3(1, T_/64, B_), 128, SM_SCO>>>(pQV, pMt0, nullptr, mask, pcwp);
    k_final<<<B_, 256>>>(lng, lnb, cW, cb, out);
}

// round 15
// speedup vs baseline: 1.0145x; 1.0145x over previous
#include <cuda_runtime.h>
#include <cstdint>
#include <math.h>

#define B_  32
#define T_  512
#define S_  64
#define D_  768
#define C_  8
#define NW_ 1536   // packed [Wqk | Wv] width

// ---------------- scratch (static device globals; allocation-free) ----------
__device__ float g_x  [B_*T_*D_];
__device__ float g_QV [B_*T_*NW_];   // cols 0..767 = Qk, 768..1535 = Vt
__device__ float g_M0 [B_*S_*D_];
__device__ float g_M1 [B_*S_*D_];
__device__ float g_Mt0[B_*S_*D_];    // tf32 shadow
__device__ float g_Mt1[B_*S_*D_];
__device__ float g_W  [B_*T_*S_];
__device__ float g_Wp [D_*NW_];
__device__ float g_gWr[D_*D_];
__device__ float g_cwp[B_*32*S_];
__device__ float g_valid[B_];

// ---------------- helpers ----------------------------------------------------
__device__ __forceinline__ float to_tf32(float f) {
    unsigned int u;
    asm("cvt.rna.tf32.f32 %0, %1;" : "=r"(u) : "f"(f));
    return __uint_as_float(u);
}

__device__ __forceinline__ void mma_tf32(float& c0, float& c1, float& c2, float& c3,
                                         float a0, float a1, float a2, float a3,
                                         float b0, float b1) {
    asm("mma.sync.aligned.m16n8k8.row.col.f32.tf32.tf32.f32 "
        "{%0,%1,%2,%3}, {%4,%5,%6,%7}, {%8,%9}, {%0,%1,%2,%3};"
        : "+f"(c0), "+f"(c1), "+f"(c2), "+f"(c3)
        : "r"(__float_as_uint(a0)), "r"(__float_as_uint(a1)),
          "r"(__float_as_uint(a2)), "r"(__float_as_uint(a3)),
          "r"(__float_as_uint(b0)), "r"(__float_as_uint(b1)));
}

__device__ __forceinline__ void cp_async16(float* dst, const float* src) {
    unsigned u = (unsigned)__cvta_generic_to_shared(dst);
    asm volatile("cp.async.cg.shared.global [%0], [%1], 16;" :: "r"(u), "l"(src));
}
#define CP_COMMIT() asm volatile("cp.async.commit_group;")
#define CP_WAIT0()  asm volatile("cp.async.wait_group 0;")
template<int N> __device__ __forceinline__ void cp_wait() {
    asm volatile("cp.async.wait_group %0;" :: "n"(N));
}

// ---------------- small kernels ---------------------------------------------
__global__ void k_embed(const int* __restrict__ ids,
                        const float* __restrict__ tok,
                        const float* __restrict__ pos) {
    int bt = blockIdx.x;
    int t  = bt % T_;
    long id = ids[bt];
    const float4* te = (const float4*)(tok + id * (long)D_);
    const float4* pe = (const float4*)(pos + (long)t * D_);
    float4* xo = (float4*)(g_x + (long)bt * D_);
    int i = threadIdx.x;
    float4 a = te[i], p4 = pe[i];
    a.x = to_tf32(a.x + p4.x); a.y = to_tf32(a.y + p4.y);
    a.z = to_tf32(a.z + p4.z); a.w = to_tf32(a.w + p4.w);
    xo[i] = a;
}

// merged setup: minit (blocks [0,6144)), prep (blocks [6144,8448)), valid (last 32)
#define NB_MINIT 6144   // B*S*D/256
#define NB_PREP  2304   // D*D/256
__global__ void k_setup(const float* __restrict__ mem,
                        const float* __restrict__ gW, const float* __restrict__ Wv,
                        const int* __restrict__ mask) {
    int bid = blockIdx.x, tid = threadIdx.x;
    if (bid < NB_MINIT) {
        int i = bid*256 + tid;
        float v = mem[i % (S_*D_)];
        g_M0[i]  = v;
        g_Mt0[i] = to_tf32(v);
    } else if (bid < NB_MINIT + NB_PREP) {
        int i = (bid - NB_MINIT)*256 + tid;
        g_gWr[i] = to_tf32(gW[i]);
        int k = i / D_, j = i % D_;
        g_Wp[(size_t)k*NW_ + D_ + j] = to_tf32(Wv[i]);
    } else {
        __shared__ int sh[256];
        int b = bid - (NB_MINIT + NB_PREP);
        int s = (mask[b*T_ + tid] > 0) + (mask[b*T_ + tid + 256] > 0);
        sh[tid] = s;
        __syncthreads();
        for (int o = 128; o > 0; o >>= 1) {
            if (tid < o) sh[tid] += sh[tid + o];
            __syncthreads();
        }
        if (tid == 0) g_valid[b] = (float)sh[0];
    }
}

// ---------------- generic tf32 GEMM, multistage cp.async ---------------------
// MODE 0 = NN, MODE 1 = NT
template<int BM, int BN, int WM, int WN, int MODE, bool CVT_A, bool CVT_B, int NST>
__global__ void __launch_bounds__((BM/WM)*(BN/WN)*32)
gemm_tc(const float* __restrict__ Ag, const float* __restrict__ Bg, float* __restrict__ Cg,
        int M, int N, int K, int lda, int ldb, int ldc)
{
    constexpr int BK = 32;
    constexpr int WARPS   = (BM/WM)*(BN/WN);
    constexpr int THREADS = WARPS*32;
    constexpr int MA = WM/16;
    constexpr int NA = WN/8;
    constexpr int ALD = 36;
    constexpr int AE  = BM*ALD;
    constexpr int BLD = (MODE==1) ? 36 : (BN+8);
    constexpr int BE  = ((MODE==1) ? BN : BK)*BLD;

    extern __shared__ float smbuf[];
    float* Abuf = smbuf;
    float* Bbuf = smbuf + NST*AE;

    const float* A = Ag;
    const float* B = Bg;
    float*       C = Cg;

    const int tid    = threadIdx.x;
    const int warpId = tid >> 5;
    const int lane   = tid & 31;
    const int g      = lane >> 2;
    const int tig    = lane & 3;
    const int warp_m = (warpId % (BM/WM)) * WM;
    const int warp_n = (warpId / (BM/WM)) * WN;
    const int rowBase = blockIdx.y * BM;
    const int colBase = blockIdx.x * BN;

    float acc[MA][NA][4];
#pragma unroll
    for (int i = 0; i < MA; i++)
#pragma unroll
        for (int j = 0; j < NA; j++) {
            acc[i][j][0]=0.f; acc[i][j][1]=0.f; acc[i][j][2]=0.f; acc[i][j][3]=0.f;
        }

    auto load_tile = [&](int kt, int s) {
        const int k0 = kt * BK;
        float* As = Abuf + s*AE;
        float* Bs = Bbuf + s*BE;
#pragma unroll
        for (int idx = tid; idx < BM*8; idx += THREADS) {
            int r = idx >> 3, c = idx & 7;
            cp_async16(As + r*ALD + 4*c, A + (long long)(rowBase + r)*lda + k0 + 4*c);
        }
        if (MODE == 1) {
#pragma unroll
            for (int idx = tid; idx < BN*8; idx += THREADS) {
                int r = idx >> 3, c = idx & 7;
                cp_async16(Bs + r*BLD + 4*c, B + (long long)(colBase + r)*ldb + k0 + 4*c);
            }
        } else {
#pragma unroll
            for (int idx = tid; idx < BK*(BN/4); idx += THREADS) {
                int r = idx / (BN/4), c = idx % (BN/4);
                cp_async16(Bs + r*BLD + 4*c, B + (long long)(k0 + r)*ldb + colBase + 4*c);
            }
        }
    };

    const int KT = K / BK;
#pragma unroll
    for (int s = 0; s < NST-1; s++) {
        if (s < KT) load_tile(s, s);
        CP_COMMIT();
    }

    for (int kt = 0; kt < KT; kt++) {
        const int pf = kt + NST - 1;
        if (pf < KT) load_tile(pf, pf % NST);
        CP_COMMIT();
        cp_wait<NST-2>();
        __syncthreads();

        const int cur = kt % NST;
        const float* As = Abuf + cur*AE;
        const float* Bs = Bbuf + cur*BE;

#pragma unroll
        for (int ks = 0; ks < 4; ks++) {
            const int kk = 8*ks;
            float a[MA][4], bf[NA][2];
#pragma unroll
            for (int ma = 0; ma < MA; ma++) {
                int mb = warp_m + 16*ma + g;
                const float* p0 = As + mb*ALD;
                const float* p1 = As + (mb+8)*ALD;
                a[ma][0] = p0[kk+tig];   a[ma][1] = p1[kk+tig];
                a[ma][2] = p0[kk+tig+4]; a[ma][3] = p1[kk+tig+4];
            }
            if (CVT_A) {
#pragma unroll
                for (int ma = 0; ma < MA; ma++)
#pragma unroll
                    for (int j = 0; j < 4; j++) a[ma][j] = to_tf32(a[ma][j]);
            }
            if (MODE == 1) {
#pragma unroll
                for (int na = 0; na < NA; na++) {
                    const float* p = Bs + (warp_n + 8*na + g)*BLD;
                    bf[na][0] = p[kk+tig]; bf[na][1] = p[kk+tig+4];
                }
            } else {
                const float* q0 = Bs + (kk + tig    )*BLD;
                const float* q1 = Bs + (kk + tig + 4)*BLD;
#pragma unroll
                for (int na = 0; na < NA; na++) {
                    int nb = warp_n + 8*na + g;
                    bf[na][0] = q0[nb]; bf[na][1] = q1[nb];
                }
            }
            if (CVT_B) {
#pragma unroll
                for (int na = 0; na < NA; na++) {
                    bf[na][0] = to_tf32(bf[na][0]);
                    bf[na][1] = to_tf32(bf[na][1]);
                }
            }
#pragma unroll
            for (int ma = 0; ma < MA; ma++)
#pragma unroll
                for (int na = 0; na < NA; na++)
                    mma_tf32(acc[ma][na][0], acc[ma][na][1], acc[ma][na][2], acc[ma][na][3],
                             a[ma][0], a[ma][1], a[ma][2], a[ma][3],
                             bf[na][0], bf[na][1]);
        }
        __syncthreads();
    }

#pragma unroll
    for (int ma = 0; ma < MA; ma++) {
        int r0 = rowBase + warp_m + 16*ma + g;
        int r1 = r0 + 8;
#pragma unroll
        for (int na = 0; na < NA; na++) {
            int cc = colBase + warp_n + 8*na + 2*tig;
            *(float2*)(C + (long long)r0*ldc + cc) =
                make_float2(to_tf32(acc[ma][na][0]), to_tf32(acc[ma][na][1]));
            *(float2*)(C + (long long)r1*ldc + cc) =
                make_float2(to_tf32(acc[ma][na][2]), to_tf32(acc[ma][na][3]));
        }
    }
}

// ---------------- fused scores+softmax (+optional colsum partials) -----------
// B operand (M slots) comes pre-rounded to tf32 (g_Mt*) -> no cvt in inner loop.
#define SCO_NST 4
__global__ void __launch_bounds__(128)
k_score_softmax(const float* __restrict__ Qk, const float* __restrict__ Mtf,
                float* __restrict__ Wout, const int* __restrict__ mask,
                float* __restrict__ csum)   // non-null => colsum partials, no W store
{
    constexpr int AE = 64*36;
    extern __shared__ float smbuf[];
    float* Abuf = smbuf;
    float* Bbuf = smbuf + SCO_NST*AE;

    const int b = blockIdx.z;
    const int rowBase = blockIdx.y * 64;
    const float* A  = Qk  + (long long)b*T_*NW_;
    const float* Bm = Mtf + (long long)b*S_*D_;

    const int tid  = threadIdx.x;
    const int w    = tid >> 5;
    const int lane = tid & 31;
    const int g    = lane >> 2;
    const int tig  = lane & 3;

    float acc[8][4];
#pragma unroll
    for (int j = 0; j < 8; j++) { acc[j][0]=0.f; acc[j][1]=0.f; acc[j][2]=0.f; acc[j][3]=0.f; }

    auto load_tile = [&](int kt, int s) {
        const int k0 = kt * 32;
        float* As = Abuf + s*AE;
        float* Bs = Bbuf + s*AE;
#pragma unroll
        for (int idx = tid; idx < 512; idx += 128) {
            int r = idx >> 3, c = idx & 7;
            cp_async16(As + r*36 + 4*c, A + (long long)(rowBase + r)*NW_ + k0 + 4*c);
        }
#pragma unroll
        for (int idx = tid; idx < 512; idx += 128) {
            int r = idx >> 3, c = idx & 7;
            cp_async16(Bs + r*36 + 4*c, Bm + (long long)r*D_ + k0 + 4*c);
        }
    };

#pragma unroll
    for (int s = 0; s < SCO_NST-1; s++) { load_tile(s, s); CP_COMMIT(); }

    for (int kt = 0; kt < 24; kt++) {
        const int pf = kt + SCO_NST - 1;
        if (pf < 24) load_tile(pf, pf % SCO_NST);
        CP_COMMIT();
        cp_wait<SCO_NST-2>();
        __syncthreads();
        const int cur = kt % SCO_NST;
        const float* As = Abuf + cur*AE;
        const float* Bs = Bbuf + cur*AE;
#pragma unroll
        for (int ks = 0; ks < 4; ks++) {
            const int kk = 8*ks;
            int mb = 16*w + g;
            const float* p0 = As + mb*36;
            const float* p1 = As + (mb+8)*36;
            float a0 = p0[kk+tig],   a1 = p1[kk+tig];
            float a2 = p0[kk+tig+4], a3 = p1[kk+tig+4];
            float bf[8][2];
#pragma unroll
            for (int na = 0; na < 8; na++) {
                const float* p = Bs + (8*na + g)*36;
                bf[na][0] = p[kk+tig]; bf[na][1] = p[kk+tig+4];
            }
#pragma unroll
            for (int na = 0; na < 8; na++)
                mma_tf32(acc[na][0], acc[na][1], acc[na][2], acc[na][3],
                         a0, a1, a2, a3, bf[na][0], bf[na][1]);
        }
        __syncthreads();
    }

    // softmax epilogue: warp owns full rows t0 = rowBase+16w+g and t1 = t0+8.
    const float scale = 0.03608439182435161f;
    float mx0 = -1e30f, mx1 = -1e30f;
#pragma unroll
    for (int na = 0; na < 8; na++) {
#pragma unroll
        for (int j = 0; j < 4; j++) {
            float v = fminf(fmaxf(acc[na][j]*scale, -20.f), 20.f);
            acc[na][j] = v;
            if (j < 2) mx0 = fmaxf(mx0, v); else mx1 = fmaxf(mx1, v);
        }
    }
    mx0 = fmaxf(mx0, __shfl_xor_sync(0xffffffffu, mx0, 1));
    mx0 = fmaxf(mx0, __shfl_xor_sync(0xffffffffu, mx0, 2));
    mx1 = fmaxf(mx1, __shfl_xor_sync(0xffffffffu, mx1, 1));
    mx1 = fmaxf(mx1, __shfl_xor_sync(0xffffffffu, mx1, 2));
    float sm0 = 0.f, sm1 = 0.f;
#pragma unroll
    for (int na = 0; na < 8; na++) {
        acc[na][0] = expf(acc[na][0] - mx0); sm0 += acc[na][0];
        acc[na][1] = expf(acc[na][1] - mx0); sm0 += acc[na][1];
        acc[na][2] = expf(acc[na][2] - mx1); sm1 += acc[na][2];
        acc[na][3] = expf(acc[na][3] - mx1); sm1 += acc[na][3];
    }
    sm0 += __shfl_xor_sync(0xffffffffu, sm0, 1);
    sm0 += __shfl_xor_sync(0xffffffffu, sm0, 2);
    sm1 += __shfl_xor_sync(0xffffffffu, sm1, 1);
    sm1 += __shfl_xor_sync(0xffffffffu, sm1, 2);
    const int t0 = rowBase + 16*w + g;
    const int t1 = t0 + 8;
    const int m0 = mask[b*T_ + t0] > 0;
    const int m1 = mask[b*T_ + t1] > 0;

    if (csum) {
        float c0 = m0 ? (1.f / sm0) : 0.f;
        float c1 = m1 ? (1.f / sm1) : 0.f;
        float part[8][2];
#pragma unroll
        for (int na = 0; na < 8; na++) {
            part[na][0] = acc[na][0]*c0 + acc[na][2]*c1;
            part[na][1] = acc[na][1]*c0 + acc[na][3]*c1;
        }
#pragma unroll
        for (int o = 4; o < 32; o <<= 1) {
#pragma unroll
            for (int na = 0; na < 8; na++) {
                part[na][0] += __shfl_xor_sync(0xffffffffu, part[na][0], o);
                part[na][1] += __shfl_xor_sync(0xffffffffu, part[na][1], o);
            }
        }
        if (g == 0) {
            float* dst = csum + ((size_t)b*32 + blockIdx.y*4 + w) * S_;
#pragma unroll
            for (int na = 0; na < 8; na++) {
                dst[8*na + 2*tig    ] = part[na][0];
                dst[8*na + 2*tig + 1] = part[na][1];
            }
        }
    } else {
        float vf  = g_valid[b];
        float mf0 = (vf > 0.f) ? (m0 ? 1.f : 0.f) : 1.f;
        float mf1 = (vf > 0.f) ? (m1 ? 1.f : 0.f) : 1.f;
        float i0 = mf0 / sm0, i1 = mf1 / sm1;
        float* r0 = Wout + ((size_t)b*T_ + t0)*S_;
        float* r1 = Wout + ((size_t)b*T_ + t1)*S_;
#pragma unroll
        for (int na = 0; na < 8; na++) {
            int cc = 8*na + 2*tig;
            *(float2*)(r0 + cc) = make_float2(to_tf32(acc[na][0]*i0), to_tf32(acc[na][1]*i0));
            *(float2*)(r1 + cc) = make_float2(to_tf32(acc[na][2]*i1), to_tf32(acc[na][3]*i1));
        }
    }
}

// ---------------- fused gate + write + memory update (3-stage) ---------------
// phase1 A = tf32 shadow of M (no cvt); epilogue reads fp32 M, writes fp32+tf32.
#define GW_NST 3
__global__ void __launch_bounds__(256)
k_gatewrite(const float* __restrict__ Mc, const float* __restrict__ Mtc,
            const float* __restrict__ gWr,
            const float* __restrict__ Wt, const float* __restrict__ Vtq,
            const float* __restrict__ gbp,
            float* __restrict__ Mn, float* __restrict__ Mtn)
{
    constexpr int AE = 2304;           // phase1: 64*36 ; phase2: 32*72
    constexpr int BE = 32*136;         // 4352
    extern __shared__ float smbuf[];
    float* Abuf = smbuf;
    float* Bbuf = smbuf + GW_NST*AE;

    const int b = blockIdx.z;
    const int colBase = blockIdx.x * 128;
    const float* Mp  = Mc  + (long long)b*S_*D_;
    const float* Mtp = Mtc + (long long)b*S_*D_;
    const float* Wp  = Wt  + (long long)b*T_*S_;
    const float* Vp  = Vtq + (long long)b*T_*NW_ + D_;

    const int tid  = threadIdx.x;
    const int wId  = tid >> 5;
    const int lane = tid & 31;
    const int g    = lane >> 2;
    const int tig  = lane & 3;
    const int warp_m = (wId & 1) * 32;
    const int warp_n = (wId >> 1) * 32;

    float accG[2][4][4], accW[2][4][4];
#pragma unroll
    for (int i = 0; i < 2; i++)
#pragma unroll
        for (int j = 0; j < 4; j++)
#pragma unroll
            for (int k = 0; k < 4; k++) { accG[i][j][k] = 0.f; accW[i][j][k] = 0.f; }

    // ---- phase 1: gate = Mt @ gWr, K = 768 ----
    auto loadG = [&](int kt, int s) {
        const int k0 = kt * 32;
        float* As = Abuf + s*AE;
        float* Bs = Bbuf + s*BE;
#pragma unroll
        for (int idx = tid; idx < 512; idx += 256) {
            int r = idx >> 3, c = idx & 7;
            cp_async16(As + r*36 + 4*c, Mtp + (long long)r*D_ + k0 + 4*c);
        }
#pragma unroll
        for (int idx = tid; idx < 1024; idx += 256) {
            int r = idx >> 5, c = idx & 31;
            cp_async16(Bs + r*136 + 4*c, gWr + (long long)(k0 + r)*D_ + colBase + 4*c);
        }
    };
#pragma unroll
    for (int s = 0; s < GW_NST-1; s++) { loadG(s, s); CP_COMMIT(); }
    for (int kt = 0; kt < 24; kt++) {
        const int pf = kt + GW_NST - 1;
        if (pf < 24) loadG(pf, pf % GW_NST);
        CP_COMMIT();
        cp_wait<GW_NST-2>();
        __syncthreads();
        const int cur = kt % GW_NST;
        const float* As = Abuf + cur*AE;
        const float* Bs = Bbuf + cur*BE;
#pragma unroll
        for (int ks = 0; ks < 4; ks++) {
            const int kk = 8*ks;
            float a[2][4], bf[4][2];
#pragma unroll
            for (int ma = 0; ma < 2; ma++) {
                int mb = warp_m + 16*ma + g;
                const float* p0 = As + mb*36;
                const float* p1 = As + (mb+8)*36;
                a[ma][0] = p0[kk+tig];   a[ma][1] = p1[kk+tig];
                a[ma][2] = p0[kk+tig+4]; a[ma][3] = p1[kk+tig+4];
            }
            const float* q0 = Bs + (kk + tig    )*136;
            const float* q1 = Bs + (kk + tig + 4)*136;
#pragma unroll
            for (int na = 0; na < 4; na++) {
                int nb = warp_n + 8*na + g;
                bf[na][0] = q0[nb]; bf[na][1] = q1[nb];
            }
#pragma unroll
            for (int ma = 0; ma < 2; ma++)
#pragma unroll
                for (int na = 0; na < 4; na++)
                    mma_tf32(accG[ma][na][0], accG[ma][na][1], accG[ma][na][2], accG[ma][na][3],
                             a[ma][0], a[ma][1], a[ma][2], a[ma][3],
                             bf[na][0], bf[na][1]);
        }
        __syncthreads();
    }
    CP_WAIT0();
    __syncthreads();

    // ---- phase 2: write = W^T @ Vt, K = 512 ----
    auto loadW = [&](int kt, int s) {
        const int k0 = kt * 32;
        float* As = Abuf + s*AE;
        float* Bs = Bbuf + s*BE;
#pragma unroll
        for (int idx = tid; idx < 512; idx += 256) {
            int r = idx >> 4, c = idx & 15;
            cp_async16(As + r*72 + 4*c, Wp + (long long)(k0 + r)*S_ + 4*c);
        }
#pragma unroll
        for (int idx = tid; idx < 1024; idx += 256) {
            int r = idx >> 5, c = idx & 31;
            cp_async16(Bs + r*136 + 4*c, Vp + (long long)(k0 + r)*NW_ + colBase + 4*c);
        }
    };
#pragma unroll
    for (int s = 0; s < GW_NST-1; s++) { loadW(s, s); CP_COMMIT(); }
    for (int kt = 0; kt < 16; kt++) {
        const int pf = kt + GW_NST - 1;
        if (pf < 16) loadW(pf, pf % GW_NST);
        CP_COMMIT();
        cp_wait<GW_NST-2>();
        __syncthreads();
        const int cur = kt % GW_NST;
        const float* As = Abuf + cur*AE;
        const float* Bs = Bbuf + cur*BE;
#pragma unroll
        for (int ks = 0; ks < 4; ks++) {
            const int kk = 8*ks;
            float a[2][4], bf[4][2];
            const float* r0 = As + (kk + tig    )*72;
            const float* r1 = As + (kk + tig + 4)*72;
#pragma unroll
            for (int ma = 0; ma < 2; ma++) {
                int mb = warp_m + 16*ma + g;
                a[ma][0] = r0[mb]; a[ma][1] = r0[mb+8];
                a[ma][2] = r1[mb]; a[ma][3] = r1[mb+8];
            }
            const float* q0 = Bs + (kk + tig    )*136;
            const float* q1 = Bs + (kk + tig + 4)*136;
#pragma unroll
            for (int na = 0; na < 4; na++) {
                int nb = warp_n + 8*na + g;
                bf[na][0] = q0[nb]; bf[na][1] = q1[nb];
            }
#pragma unroll
            for (int ma = 0; ma < 2; ma++)
#pragma unroll
                for (int na = 0; na < 4; na++)
                    mma_tf32(accW[ma][na][0], accW[ma][na][1], accW[ma][na][2], accW[ma][na][3],
                             a[ma][0], a[ma][1], a[ma][2], a[ma][3],
                             bf[na][0], bf[na][1]);
        }
        __syncthreads();
    }

    // ---- epilogue: M update (fp32 state + tf32 shadow) ----
    float* Mo  = Mn  + (long long)b*S_*D_;
    float* Mto = Mtn + (long long)b*S_*D_;
#pragma unroll
    for (int ma = 0; ma < 2; ma++) {
        int s0 = warp_m + 16*ma + g;
        int s1 = s0 + 8;
#pragma unroll
        for (int na = 0; na < 4; na++) {
            int cc = colBase + warp_n + 8*na + 2*tig;
            float2 gb2 = *(const float2*)(gbp + cc);
#pragma unroll
            for (int rr = 0; rr < 2; rr++) {
                int row = rr ? s1 : s0;
                float gx = accG[ma][na][2*rr]   + gb2.x;
                float gy = accG[ma][na][2*rr+1] + gb2.y;
                float sx = 1.f / (1.f + expf(-gx));
                float sy = 1.f / (1.f + expf(-gy));
                float2 mo = *(const float2*)(Mp + (long long)row*D_ + cc);
                float nx = fminf(fmaxf(0.9f*mo.x + 0.1f*sx*accW[ma][na][2*rr],   -50.f), 50.f);
                float ny = fminf(fmaxf(0.9f*mo.y + 0.1f*sy*accW[ma][na][2*rr+1], -50.f), 50.f);
                *(float2*)(Mo  + (long long)row*D_ + cc) = make_float2(nx, ny);
                *(float2*)(Mto + (long long)row*D_ + cc) =
                    make_float2(to_tf32(nx), to_tf32(ny));
            }
        }
    }
}

// ---------------- pooled; LayerNorm; logits ----------------------------------
__global__ void k_final(const float* __restrict__ ln_g, const float* __restrict__ ln_b,
                        const float* __restrict__ cls_W, const float* __restrict__ cls_b,
                        float* __restrict__ out)
{
    __shared__ float cw[S_];
    __shared__ float p[D_];
    __shared__ float red[256];
    int b = blockIdx.x, tid = threadIdx.x;
    if (tid < S_) {
        float a = 0.f;
        const float* cp = g_cwp + (size_t)b*32*S_ + tid;
#pragma unroll
        for (int i = 0; i < 32; i++) a += cp[i*S_];
        cw[tid] = a;
    }
    __syncthreads();
    float invn = 1.f / fmaxf(g_valid[b], 1.f);
    for (int d = tid; d < D_; d += 256) {
        float acc = 0.f;
        const float* Mb = g_M0 + (size_t)b*S_*D_ + d;
#pragma unroll 8
        for (int s = 0; s < S_; s++) acc += cw[s] * Mb[s*D_];
        p[d] = acc * invn;
    }
    __syncthreads();
    float ls = 0.f;
    for (int d = tid; d < D_; d += 256) ls += p[d];
    red[tid] = ls; __syncthreads();
    for (int o = 128; o > 0; o >>= 1) { if (tid < o) red[tid] += red[tid + o]; __syncthreads(); }
    float mu = red[0] / D_;
    __syncthreads();
    float lv = 0.f;
    for (int d = tid; d < D_; d += 256) { float z = p[d] - mu; lv += z*z; }
    red[tid] = lv; __syncthreads();
    for (int o = 128; o > 0; o >>= 1) { if (tid < o) red[tid] += red[tid + o]; __syncthreads(); }
    float rs = rsqrtf(red[0] / D_ + 1e-5f);
    __syncthreads();
    for (int d = tid; d < D_; d += 256)
        p[d] = (p[d] - mu) * rs * ln_g[d] + ln_b[d];
    __syncthreads();
    int w = tid >> 5, lane = tid & 31;
    float acc = 0.f;
    for (int d = lane; d < D_; d += 32) acc += p[d] * cls_W[d*C_ + w];
#pragma unroll
    for (int o = 16; o > 0; o >>= 1) acc += __shfl_down_sync(0xffffffffu, acc, o);
    if (lane == 0) {
        float v = acc + cls_b[w];
        if (!isfinite(v)) v = 0.f;
        out[b*C_ + w] = v;
    }
}

// ---------------- launch -----------------------------------------------------
extern "C" void kernel_launch(void* const* d_in, const int* in_sizes, int n_in,
                              void* d_out, int out_size)
{
    const int*   ids  = (const int*)  d_in[0];
    const int*   mask = (const int*)  d_in[1];
    const float* tok  = (const float*)d_in[2];
    const float* pos  = (const float*)d_in[3];
    const float* Wq   = (const float*)d_in[4];
    const float* Wk   = (const float*)d_in[5];
    const float* Wv   = (const float*)d_in[6];
    const float* gW   = (const float*)d_in[7];
    const float* gb   = (const float*)d_in[8];
    const float* lng  = (const float*)d_in[9];
    const float* lnb  = (const float*)d_in[10];
    const float* cW   = (const float*)d_in[11];
    const float* cb   = (const float*)d_in[12];
    const float* mem  = (const float*)d_in[13];
    float* out = (float*)d_out;

    float *px, *pQV, *pM0, *pM1, *pMt0, *pMt1, *pW, *pWp, *pgWr, *pcwp;
    cudaGetSymbolAddress((void**)&px,   g_x);
    cudaGetSymbolAddress((void**)&pQV,  g_QV);
    cudaGetSymbolAddress((void**)&pM0,  g_M0);
    cudaGetSymbolAddress((void**)&pM1,  g_M1);
    cudaGetSymbolAddress((void**)&pMt0, g_Mt0);
    cudaGetSymbolAddress((void**)&pMt1, g_Mt1);
    cudaGetSymbolAddress((void**)&pW,   g_W);
    cudaGetSymbolAddress((void**)&pWp,  g_Wp);
    cudaGetSymbolAddress((void**)&pgWr, g_gWr);
    cudaGetSymbolAddress((void**)&pcwp, g_cwp);

    auto kWqk = gemm_tc<128,128,64,32, 1, true , true , 3>;  // Wqk = Wq @ Wk^T
    auto kBig = gemm_tc<128,128,64,32, 0, false, false, 3>;  // QV = x @ [Wqk|Wv]

    const int SM_WQK = 3*(128*36 + 128*36)*4;  // 110592
    const int SM_BIG = 3*(128*36 +  32*136)*4; // 107520
    const int SM_SCO = SCO_NST*2*(64*36)*4;    // 73728
    const int SM_GW  = GW_NST*(2304 + 4352)*4; // 79872

    cudaFuncSetAttribute(kWqk, cudaFuncAttributeMaxDynamicSharedMemorySize, SM_WQK);
    cudaFuncSetAttribute(kBig, cudaFuncAttributeMaxDynamicSharedMemorySize, SM_BIG);
    cudaFuncSetAttribute(k_score_softmax, cudaFuncAttributeMaxDynamicSharedMemorySize, SM_SCO);
    cudaFuncSetAttribute(k_gatewrite,     cudaFuncAttributeMaxDynamicSharedMemorySize, SM_GW);

    k_embed<<<B_*T_, 192>>>(ids, tok, pos);
    kWqk<<<dim3(D_/128, D_/128, 1), 256, SM_WQK>>>(Wq, Wk, pWp, D_, D_, D_, D_, D_, NW_);
    k_setup<<<NB_MINIT + NB_PREP + B_, 256>>>(mem, gW, Wv, mask);
    kBig<<<dim3(NW_/128, (B_*T_)/128, 1), 256, SM_BIG>>>(px, pWp, pQV, B_*T_, NW_, D_, D_, NW_, NW_);

    float* Mbuf [2] = {pM0,  pM1};
    float* Mtbuf[2] = {pMt0, pMt1};
    for (int step = 0; step < 4; step++) {
        const float* Mc  = Mbuf [step & 1];
        const float* Mtc = Mtbuf[step & 1];
        float*       Mn  = Mbuf [(step & 1) ^ 1];
        float*       Mtn = Mtbuf[(step & 1) ^ 1];
        k_score_softmax<<<dim3(1, T_/64, B_), 128, SM_SCO>>>(pQV, Mtc, pW, mask, nullptr);
        k_gatewrite<<<dim3(D_/128, 1, B_), 256, SM_GW>>>(Mc, Mtc, pgWr, pW, pQV, gb, Mn, Mtn);
    }
    // after 4 steps state is back in M0/Mt0; final read -> colsum partials only
    k_score_softmax<<<dim3(1, T_/64, B_), 128, SM_SCO>>>(pQV, pMt0, nullptr, mask, pcwp);
    k_final<<<B_, 256>>>(lng, lnb, cW, cb, out);
}

// round 16
// speedup vs baseline: 1.0370x; 1.0222x over previous
#include <cuda_runtime.h>
#include <cstdint>
#include <math.h>

#define B_  32
#define T_  512
#define S_  64
#define D_  768
#define C_  8
#define NW_ 1536   // packed [Wqk | Wv] width

// ---------------- scratch (static device globals; allocation-free) ----------
__device__ float g_x  [B_*T_*D_];
__device__ float g_QV [B_*T_*NW_];   // cols 0..767 = Qk, 768..1535 = Vt
__device__ float g_M0 [B_*S_*D_];
__device__ float g_M1 [B_*S_*D_];
__device__ float g_Mt0[B_*S_*D_];    // tf32 shadow
__device__ float g_Mt1[B_*S_*D_];
__device__ float g_W  [B_*T_*S_];
__device__ float g_Wp [D_*NW_];
__device__ float g_gWr[D_*D_];
__device__ float g_cwp[B_*32*S_];
__device__ float g_valid[B_];

// ---------------- helpers ----------------------------------------------------
__device__ __forceinline__ float to_tf32(float f) {
    unsigned int u;
    asm("cvt.rna.tf32.f32 %0, %1;" : "=r"(u) : "f"(f));
    return __uint_as_float(u);
}

__device__ __forceinline__ void mma_tf32(float& c0, float& c1, float& c2, float& c3,
                                         float a0, float a1, float a2, float a3,
                                         float b0, float b1) {
    asm("mma.sync.aligned.m16n8k8.row.col.f32.tf32.tf32.f32 "
        "{%0,%1,%2,%3}, {%4,%5,%6,%7}, {%8,%9}, {%0,%1,%2,%3};"
        : "+f"(c0), "+f"(c1), "+f"(c2), "+f"(c3)
        : "r"(__float_as_uint(a0)), "r"(__float_as_uint(a1)),
          "r"(__float_as_uint(a2)), "r"(__float_as_uint(a3)),
          "r"(__float_as_uint(b0)), "r"(__float_as_uint(b1)));
}

__device__ __forceinline__ void cp_async16(float* dst, const float* src) {
    unsigned u = (unsigned)__cvta_generic_to_shared(dst);
    asm volatile("cp.async.cg.shared.global [%0], [%1], 16;" :: "r"(u), "l"(src));
}
#define CP_COMMIT() asm volatile("cp.async.commit_group;")
#define CP_WAIT0()  asm volatile("cp.async.wait_group 0;")
template<int N> __device__ __forceinline__ void cp_wait() {
    asm volatile("cp.async.wait_group %0;" :: "n"(N));
}

// ---------------- small kernels ---------------------------------------------
__global__ void k_embed(const int* __restrict__ ids,
                        const float* __restrict__ tok,
                        const float* __restrict__ pos) {
    int bt = blockIdx.x;
    int t  = bt % T_;
    long id = ids[bt];
    const float4* te = (const float4*)(tok + id * (long)D_);
    const float4* pe = (const float4*)(pos + (long)t * D_);
    float4* xo = (float4*)(g_x + (long)bt * D_);
    int i = threadIdx.x;
    float4 a = te[i], p4 = pe[i];
    a.x = to_tf32(a.x + p4.x); a.y = to_tf32(a.y + p4.y);
    a.z = to_tf32(a.z + p4.z); a.w = to_tf32(a.w + p4.w);
    xo[i] = a;
}

// merged setup: minit (blocks [0,6144)), prep (blocks [6144,8448)), valid (last 32)
#define NB_MINIT 6144   // B*S*D/256
#define NB_PREP  2304   // D*D/256
__global__ void k_setup(const float* __restrict__ mem,
                        const float* __restrict__ gW, const float* __restrict__ Wv,
                        const int* __restrict__ mask) {
    int bid = blockIdx.x, tid = threadIdx.x;
    if (bid < NB_MINIT) {
        int i = bid*256 + tid;
        float v = mem[i % (S_*D_)];
        g_M0[i]  = v;
        g_Mt0[i] = to_tf32(v);
    } else if (bid < NB_MINIT + NB_PREP) {
        int i = (bid - NB_MINIT)*256 + tid;
        g_gWr[i] = to_tf32(gW[i]);
        int k = i / D_, j = i % D_;
        g_Wp[(size_t)k*NW_ + D_ + j] = to_tf32(Wv[i]);
    } else {
        __shared__ int sh[256];
        int b = bid - (NB_MINIT + NB_PREP);
        int s = (mask[b*T_ + tid] > 0) + (mask[b*T_ + tid + 256] > 0);
        sh[tid] = s;
        __syncthreads();
        for (int o = 128; o > 0; o >>= 1) {
            if (tid < o) sh[tid] += sh[tid + o];
            __syncthreads();
        }
        if (tid == 0) g_valid[b] = (float)sh[0];
    }
}

// ---------------- generic tf32 GEMM, multistage cp.async, single-sync --------
// MODE 0 = NN, MODE 1 = NT
template<int BM, int BN, int WM, int WN, int MODE, bool CVT_A, bool CVT_B, int NST>
__global__ void __launch_bounds__((BM/WM)*(BN/WN)*32)
gemm_tc(const float* __restrict__ Ag, const float* __restrict__ Bg, float* __restrict__ Cg,
        int M, int N, int K, int lda, int ldb, int ldc)
{
    constexpr int BK = 32;
    constexpr int WARPS   = (BM/WM)*(BN/WN);
    constexpr int THREADS = WARPS*32;
    constexpr int MA = WM/16;
    constexpr int NA = WN/8;
    constexpr int ALD = 36;
    constexpr int AE  = BM*ALD;
    constexpr int BLD = (MODE==1) ? 36 : (BN+8);
    constexpr int BE  = ((MODE==1) ? BN : BK)*BLD;

    extern __shared__ float smbuf[];
    float* Abuf = smbuf;
    float* Bbuf = smbuf + NST*AE;

    const float* A = Ag;
    const float* B = Bg;
    float*       C = Cg;

    const int tid    = threadIdx.x;
    const int warpId = tid >> 5;
    const int lane   = tid & 31;
    const int g      = lane >> 2;
    const int tig    = lane & 3;
    const int warp_m = (warpId % (BM/WM)) * WM;
    const int warp_n = (warpId / (BM/WM)) * WN;
    const int rowBase = blockIdx.y * BM;
    const int colBase = blockIdx.x * BN;

    float acc[MA][NA][4];
#pragma unroll
    for (int i = 0; i < MA; i++)
#pragma unroll
        for (int j = 0; j < NA; j++) {
            acc[i][j][0]=0.f; acc[i][j][1]=0.f; acc[i][j][2]=0.f; acc[i][j][3]=0.f;
        }

    auto load_tile = [&](int kt, int s) {
        const int k0 = kt * BK;
        float* As = Abuf + s*AE;
        float* Bs = Bbuf + s*BE;
#pragma unroll
        for (int idx = tid; idx < BM*8; idx += THREADS) {
            int r = idx >> 3, c = idx & 7;
            cp_async16(As + r*ALD + 4*c, A + (long long)(rowBase + r)*lda + k0 + 4*c);
        }
        if (MODE == 1) {
#pragma unroll
            for (int idx = tid; idx < BN*8; idx += THREADS) {
                int r = idx >> 3, c = idx & 7;
                cp_async16(Bs + r*BLD + 4*c, B + (long long)(colBase + r)*ldb + k0 + 4*c);
            }
        } else {
#pragma unroll
            for (int idx = tid; idx < BK*(BN/4); idx += THREADS) {
                int r = idx / (BN/4), c = idx % (BN/4);
                cp_async16(Bs + r*BLD + 4*c, B + (long long)(k0 + r)*ldb + colBase + 4*c);
            }
        }
    };

    const int KT = K / BK;
#pragma unroll
    for (int s = 0; s < NST-1; s++) {
        if (s < KT) load_tile(s, s);
        CP_COMMIT();
    }

    for (int kt = 0; kt < KT; kt++) {
        cp_wait<NST-2>();
        __syncthreads();               // stage kt%NST ready; stage (kt-1)%NST fully consumed
        const int pf = kt + NST - 1;
        if (pf < KT) load_tile(pf, pf % NST);
        CP_COMMIT();

        const int cur = kt % NST;
        const float* As = Abuf + cur*AE;
        const float* Bs = Bbuf + cur*BE;

#pragma unroll
        for (int ks = 0; ks < 4; ks++) {
            const int kk = 8*ks;
            float a[MA][4], bf[NA][2];
#pragma unroll
            for (int ma = 0; ma < MA; ma++) {
                int mb = warp_m + 16*ma + g;
                const float* p0 = As + mb*ALD;
                const float* p1 = As + (mb+8)*ALD;
                a[ma][0] = p0[kk+tig];   a[ma][1] = p1[kk+tig];
                a[ma][2] = p0[kk+tig+4]; a[ma][3] = p1[kk+tig+4];
            }
            if (CVT_A) {
#pragma unroll
                for (int ma = 0; ma < MA; ma++)
#pragma unroll
                    for (int j = 0; j < 4; j++) a[ma][j] = to_tf32(a[ma][j]);
            }
            if (MODE == 1) {
#pragma unroll
                for (int na = 0; na < NA; na++) {
                    const float* p = Bs + (warp_n + 8*na + g)*BLD;
                    bf[na][0] = p[kk+tig]; bf[na][1] = p[kk+tig+4];
                }
            } else {
                const float* q0 = Bs + (kk + tig    )*BLD;
                const float* q1 = Bs + (kk + tig + 4)*BLD;
#pragma unroll
                for (int na = 0; na < NA; na++) {
                    int nb = warp_n + 8*na + g;
                    bf[na][0] = q0[nb]; bf[na][1] = q1[nb];
                }
            }
            if (CVT_B) {
#pragma unroll
                for (int na = 0; na < NA; na++) {
                    bf[na][0] = to_tf32(bf[na][0]);
                    bf[na][1] = to_tf32(bf[na][1]);
                }
            }
#pragma unroll
            for (int ma = 0; ma < MA; ma++)
#pragma unroll
                for (int na = 0; na < NA; na++)
                    mma_tf32(acc[ma][na][0], acc[ma][na][1], acc[ma][na][2], acc[ma][na][3],
                             a[ma][0], a[ma][1], a[ma][2], a[ma][3],
                             bf[na][0], bf[na][1]);
        }
    }

#pragma unroll
    for (int ma = 0; ma < MA; ma++) {
        int r0 = rowBase + warp_m + 16*ma + g;
        int r1 = r0 + 8;
#pragma unroll
        for (int na = 0; na < NA; na++) {
            int cc = colBase + warp_n + 8*na + 2*tig;
            *(float2*)(C + (long long)r0*ldc + cc) =
                make_float2(to_tf32(acc[ma][na][0]), to_tf32(acc[ma][na][1]));
            *(float2*)(C + (long long)r1*ldc + cc) =
                make_float2(to_tf32(acc[ma][na][2]), to_tf32(acc[ma][na][3]));
        }
    }
}

// ---------------- fused scores+softmax (+optional colsum partials) -----------
// B operand (M slots) comes pre-rounded to tf32 (g_Mt*) -> no cvt in inner loop.
#define SCO_NST 4
__global__ void __launch_bounds__(128)
k_score_softmax(const float* __restrict__ Qk, const float* __restrict__ Mtf,
                float* __restrict__ Wout, const int* __restrict__ mask,
                float* __restrict__ csum)   // non-null => colsum partials, no W store
{
    constexpr int AE = 64*36;
    extern __shared__ float smbuf[];
    float* Abuf = smbuf;
    float* Bbuf = smbuf + SCO_NST*AE;

    const int b = blockIdx.z;
    const int rowBase = blockIdx.y * 64;
    const float* A  = Qk  + (long long)b*T_*NW_;
    const float* Bm = Mtf + (long long)b*S_*D_;

    const int tid  = threadIdx.x;
    const int w    = tid >> 5;
    const int lane = tid & 31;
    const int g    = lane >> 2;
    const int tig  = lane & 3;

    float acc[8][4];
#pragma unroll
    for (int j = 0; j < 8; j++) { acc[j][0]=0.f; acc[j][1]=0.f; acc[j][2]=0.f; acc[j][3]=0.f; }

    auto load_tile = [&](int kt, int s) {
        const int k0 = kt * 32;
        float* As = Abuf + s*AE;
        float* Bs = Bbuf + s*AE;
#pragma unroll
        for (int idx = tid; idx < 512; idx += 128) {
            int r = idx >> 3, c = idx & 7;
            cp_async16(As + r*36 + 4*c, A + (long long)(rowBase + r)*NW_ + k0 + 4*c);
        }
#pragma unroll
        for (int idx = tid; idx < 512; idx += 128) {
            int r = idx >> 3, c = idx & 7;
            cp_async16(Bs + r*36 + 4*c, Bm + (long long)r*D_ + k0 + 4*c);
        }
    };

#pragma unroll
    for (int s = 0; s < SCO_NST-1; s++) { load_tile(s, s); CP_COMMIT(); }

    for (int kt = 0; kt < 24; kt++) {
        cp_wait<SCO_NST-2>();
        __syncthreads();
        const int pf = kt + SCO_NST - 1;
        if (pf < 24) load_tile(pf, pf % SCO_NST);
        CP_COMMIT();

        const int cur = kt % SCO_NST;
        const float* As = Abuf + cur*AE;
        const float* Bs = Bbuf + cur*AE;
#pragma unroll
        for (int ks = 0; ks < 4; ks++) {
            const int kk = 8*ks;
            int mb = 16*w + g;
            const float* p0 = As + mb*36;
            const float* p1 = As + (mb+8)*36;
            float a0 = p0[kk+tig],   a1 = p1[kk+tig];
            float a2 = p0[kk+tig+4], a3 = p1[kk+tig+4];
            float bf[8][2];
#pragma unroll
            for (int na = 0; na < 8; na++) {
                const float* p = Bs + (8*na + g)*36;
                bf[na][0] = p[kk+tig]; bf[na][1] = p[kk+tig+4];
            }
#pragma unroll
            for (int na = 0; na < 8; na++)
                mma_tf32(acc[na][0], acc[na][1], acc[na][2], acc[na][3],
                         a0, a1, a2, a3, bf[na][0], bf[na][1]);
        }
    }

    // softmax epilogue: warp owns full rows t0 = rowBase+16w+g and t1 = t0+8.
    const float scale = 0.03608439182435161f;
    float mx0 = -1e30f, mx1 = -1e30f;
#pragma unroll
    for (int na = 0; na < 8; na++) {
#pragma unroll
        for (int j = 0; j < 4; j++) {
            float v = fminf(fmaxf(acc[na][j]*scale, -20.f), 20.f);
            acc[na][j] = v;
            if (j < 2) mx0 = fmaxf(mx0, v); else mx1 = fmaxf(mx1, v);
        }
    }
    mx0 = fmaxf(mx0, __shfl_xor_sync(0xffffffffu, mx0, 1));
    mx0 = fmaxf(mx0, __shfl_xor_sync(0xffffffffu, mx0, 2));
    mx1 = fmaxf(mx1, __shfl_xor_sync(0xffffffffu, mx1, 1));
    mx1 = fmaxf(mx1, __shfl_xor_sync(0xffffffffu, mx1, 2));
    float sm0 = 0.f, sm1 = 0.f;
#pragma unroll
    for (int na = 0; na < 8; na++) {
        acc[na][0] = expf(acc[na][0] - mx0); sm0 += acc[na][0];
        acc[na][1] = expf(acc[na][1] - mx0); sm0 += acc[na][1];
        acc[na][2] = expf(acc[na][2] - mx1); sm1 += acc[na][2];
        acc[na][3] = expf(acc[na][3] - mx1); sm1 += acc[na][3];
    }
    sm0 += __shfl_xor_sync(0xffffffffu, sm0, 1);
    sm0 += __shfl_xor_sync(0xffffffffu, sm0, 2);
    sm1 += __shfl_xor_sync(0xffffffffu, sm1, 1);
    sm1 += __shfl_xor_sync(0xffffffffu, sm1, 2);
    const int t0 = rowBase + 16*w + g;
    const int t1 = t0 + 8;
    const int m0 = mask[b*T_ + t0] > 0;
    const int m1 = mask[b*T_ + t1] > 0;

    if (csum) {
        float c0 = m0 ? (1.f / sm0) : 0.f;
        float c1 = m1 ? (1.f / sm1) : 0.f;
        float part[8][2];
#pragma unroll
        for (int na = 0; na < 8; na++) {
            part[na][0] = acc[na][0]*c0 + acc[na][2]*c1;
            part[na][1] = acc[na][1]*c0 + acc[na][3]*c1;
        }
#pragma unroll
        for (int o = 4; o < 32; o <<= 1) {
#pragma unroll
            for (int na = 0; na < 8; na++) {
                part[na][0] += __shfl_xor_sync(0xffffffffu, part[na][0], o);
                part[na][1] += __shfl_xor_sync(0xffffffffu, part[na][1], o);
            }
        }
        if (g == 0) {
            float* dst = csum + ((size_t)b*32 + blockIdx.y*4 + w) * S_;
#pragma unroll
            for (int na = 0; na < 8; na++) {
                dst[8*na + 2*tig    ] = part[na][0];
                dst[8*na + 2*tig + 1] = part[na][1];
            }
        }
    } else {
        float vf  = g_valid[b];
        float mf0 = (vf > 0.f) ? (m0 ? 1.f : 0.f) : 1.f;
        float mf1 = (vf > 0.f) ? (m1 ? 1.f : 0.f) : 1.f;
        float i0 = mf0 / sm0, i1 = mf1 / sm1;
        float* r0 = Wout + ((size_t)b*T_ + t0)*S_;
        float* r1 = Wout + ((size_t)b*T_ + t1)*S_;
#pragma unroll
        for (int na = 0; na < 8; na++) {
            int cc = 8*na + 2*tig;
            *(float2*)(r0 + cc) = make_float2(to_tf32(acc[na][0]*i0), to_tf32(acc[na][1]*i0));
            *(float2*)(r1 + cc) = make_float2(to_tf32(acc[na][2]*i1), to_tf32(acc[na][3]*i1));
        }
    }
}

// ---------------- fused gate + write + memory update (3-stage, single-sync) --
#define GW_NST 3
__global__ void __launch_bounds__(256)
k_gatewrite(const float* __restrict__ Mc, const float* __restrict__ Mtc,
            const float* __restrict__ gWr,
            const float* __restrict__ Wt, const float* __restrict__ Vtq,
            const float* __restrict__ gbp,
            float* __restrict__ Mn, float* __restrict__ Mtn)
{
    constexpr int AE = 2304;           // phase1: 64*36 ; phase2: 32*72
    constexpr int BE = 32*136;         // 4352
    extern __shared__ float smbuf[];
    float* Abuf = smbuf;
    float* Bbuf = smbuf + GW_NST*AE;

    const int b = blockIdx.z;
    const int colBase = blockIdx.x * 128;
    const float* Mp  = Mc  + (long long)b*S_*D_;
    const float* Mtp = Mtc + (long long)b*S_*D_;
    const float* Wp  = Wt  + (long long)b*T_*S_;
    const float* Vp  = Vtq + (long long)b*T_*NW_ + D_;

    const int tid  = threadIdx.x;
    const int wId  = tid >> 5;
    const int lane = tid & 31;
    const int g    = lane >> 2;
    const int tig  = lane & 3;
    const int warp_m = (wId & 1) * 32;
    const int warp_n = (wId >> 1) * 32;

    float accG[2][4][4], accW[2][4][4];
#pragma unroll
    for (int i = 0; i < 2; i++)
#pragma unroll
        for (int j = 0; j < 4; j++)
#pragma unroll
            for (int k = 0; k < 4; k++) { accG[i][j][k] = 0.f; accW[i][j][k] = 0.f; }

    // ---- phase 1: gate = Mt @ gWr, K = 768 ----
    auto loadG = [&](int kt, int s) {
        const int k0 = kt * 32;
        float* As = Abuf + s*AE;
        float* Bs = Bbuf + s*BE;
#pragma unroll
        for (int idx = tid; idx < 512; idx += 256) {
            int r = idx >> 3, c = idx & 7;
            cp_async16(As + r*36 + 4*c, Mtp + (long long)r*D_ + k0 + 4*c);
        }
#pragma unroll
        for (int idx = tid; idx < 1024; idx += 256) {
            int r = idx >> 5, c = idx & 31;
            cp_async16(Bs + r*136 + 4*c, gWr + (long long)(k0 + r)*D_ + colBase + 4*c);
        }
    };
#pragma unroll
    for (int s = 0; s < GW_NST-1; s++) { loadG(s, s); CP_COMMIT(); }
    for (int kt = 0; kt < 24; kt++) {
        cp_wait<GW_NST-2>();
        __syncthreads();
        const int pf = kt + GW_NST - 1;
        if (pf < 24) loadG(pf, pf % GW_NST);
        CP_COMMIT();

        const int cur = kt % GW_NST;
        const float* As = Abuf + cur*AE;
        const float* Bs = Bbuf + cur*BE;
#pragma unroll
        for (int ks = 0; ks < 4; ks++) {
            const int kk = 8*ks;
            float a[2][4], bf[4][2];
#pragma unroll
            for (int ma = 0; ma < 2; ma++) {
                int mb = warp_m + 16*ma + g;
                const float* p0 = As + mb*36;
                const float* p1 = As + (mb+8)*36;
                a[ma][0] = p0[kk+tig];   a[ma][1] = p1[kk+tig];
                a[ma][2] = p0[kk+tig+4]; a[ma][3] = p1[kk+tig+4];
            }
            const float* q0 = Bs + (kk + tig    )*136;
            const float* q1 = Bs + (kk + tig + 4)*136;
#pragma unroll
            for (int na = 0; na < 4; na++) {
                int nb = warp_n + 8*na + g;
                bf[na][0] = q0[nb]; bf[na][1] = q1[nb];
            }
#pragma unroll
            for (int ma = 0; ma < 2; ma++)
#pragma unroll
                for (int na = 0; na < 4; na++)
                    mma_tf32(accG[ma][na][0], accG[ma][na][1], accG[ma][na][2], accG[ma][na][3],
                             a[ma][0], a[ma][1], a[ma][2], a[ma][3],
                             bf[na][0], bf[na][1]);
        }
    }
    CP_WAIT0();
    __syncthreads();

    // ---- phase 2: write = W^T @ Vt, K = 512 ----
    auto loadW = [&](int kt, int s) {
        const int k0 = kt * 32;
        float* As = Abuf + s*AE;
        float* Bs = Bbuf + s*BE;
#pragma unroll
        for (int idx = tid; idx < 512; idx += 256) {
            int r = idx >> 4, c = idx & 15;
            cp_async16(As + r*72 + 4*c, Wp + (long long)(k0 + r)*S_ + 4*c);
        }
#pragma unroll
        for (int idx = tid; idx < 1024; idx += 256) {
            int r = idx >> 5, c = idx & 31;
            cp_async16(Bs + r*136 + 4*c, Vp + (long long)(k0 + r)*NW_ + colBase + 4*c);
        }
    };
#pragma unroll
    for (int s = 0; s < GW_NST-1; s++) { loadW(s, s); CP_COMMIT(); }
    for (int kt = 0; kt < 16; kt++) {
        cp_wait<GW_NST-2>();
        __syncthreads();
        const int pf = kt + GW_NST - 1;
        if (pf < 16) loadW(pf, pf % GW_NST);
        CP_COMMIT();

        const int cur = kt % GW_NST;
        const float* As = Abuf + cur*AE;
        const float* Bs = Bbuf + cur*BE;
#pragma unroll
        for (int ks = 0; ks < 4; ks++) {
            const int kk = 8*ks;
            float a[2][4], bf[4][2];
            const float* r0 = As + (kk + tig    )*72;
            const float* r1 = As + (kk + tig + 4)*72;
#pragma unroll
            for (int ma = 0; ma < 2; ma++) {
                int mb = warp_m + 16*ma + g;
                a[ma][0] = r0[mb]; a[ma][1] = r0[mb+8];
                a[ma][2] = r1[mb]; a[ma][3] = r1[mb+8];
            }
            const float* q0 = Bs + (kk + tig    )*136;
            const float* q1 = Bs + (kk + tig + 4)*136;
#pragma unroll
            for (int na = 0; na < 4; na++) {
                int nb = warp_n + 8*na + g;
                bf[na][0] = q0[nb]; bf[na][1] = q1[nb];
            }
#pragma unroll
            for (int ma = 0; ma < 2; ma++)
#pragma unroll
                for (int na = 0; na < 4; na++)
                    mma_tf32(accW[ma][na][0], accW[ma][na][1], accW[ma][na][2], accW[ma][na][3],
                             a[ma][0], a[ma][1], a[ma][2], a[ma][3],
                             bf[na][0], bf[na][1]);
        }
    }

    // ---- epilogue: M update (fp32 state + tf32 shadow) ----
    float* Mo  = Mn  + (long long)b*S_*D_;
    float* Mto = Mtn + (long long)b*S_*D_;
#pragma unroll
    for (int ma = 0; ma < 2; ma++) {
        int s0 = warp_m + 16*ma + g;
        int s1 = s0 + 8;
#pragma unroll
        for (int na = 0; na < 4; na++) {
            int cc = colBase + warp_n + 8*na + 2*tig;
            float2 gb2 = *(const float2*)(gbp + cc);
#pragma unroll
            for (int rr = 0; rr < 2; rr++) {
                int row = rr ? s1 : s0;
                float gx = accG[ma][na][2*rr]   + gb2.x;
                float gy = accG[ma][na][2*rr+1] + gb2.y;
                float sx = 1.f / (1.f + expf(-gx));
                float sy = 1.f / (1.f + expf(-gy));
                float2 mo = *(const float2*)(Mp + (long long)row*D_ + cc);
                float nx = fminf(fmaxf(0.9f*mo.x + 0.1f*sx*accW[ma][na][2*rr],   -50.f), 50.f);
                float ny = fminf(fmaxf(0.9f*mo.y + 0.1f*sy*accW[ma][na][2*rr+1], -50.f), 50.f);
                *(float2*)(Mo  + (long long)row*D_ + cc) = make_float2(nx, ny);
                *(float2*)(Mto + (long long)row*D_ + cc) =
                    make_float2(to_tf32(nx), to_tf32(ny));
            }
        }
    }
}

// ---------------- pooled; LayerNorm; logits ----------------------------------
__global__ void k_final(const float* __restrict__ ln_g, const float* __restrict__ ln_b,
                        const float* __restrict__ cls_W, const float* __restrict__ cls_b,
                        float* __restrict__ out)
{
    __shared__ float cw[S_];
    __shared__ float p[D_];
    __shared__ float red[256];
    int b = blockIdx.x, tid = threadIdx.x;
    if (tid < S_) {
        float a = 0.f;
        const float* cp = g_cwp + (size_t)b*32*S_ + tid;
#pragma unroll
        for (int i = 0; i < 32; i++) a += cp[i*S_];
        cw[tid] = a;
    }
    __syncthreads();
    float invn = 1.f / fmaxf(g_valid[b], 1.f);
    for (int d = tid; d < D_; d += 256) {
        float acc = 0.f;
        const float* Mb = g_M0 + (size_t)b*S_*D_ + d;
#pragma unroll 8
        for (int s = 0; s < S_; s++) acc += cw[s] * Mb[s*D_];
        p[d] = acc * invn;
    }
    __syncthreads();
    float ls = 0.f;
    for (int d = tid; d < D_; d += 256) ls += p[d];
    red[tid] = ls; __syncthreads();
    for (int o = 128; o > 0; o >>= 1) { if (tid < o) red[tid] += red[tid + o]; __syncthreads(); }
    float mu = red[0] / D_;
    __syncthreads();
    float lv = 0.f;
    for (int d = tid; d < D_; d += 256) { float z = p[d] - mu; lv += z*z; }
    red[tid] = lv; __syncthreads();
    for (int o = 128; o > 0; o >>= 1) { if (tid < o) red[tid] += red[tid + o]; __syncthreads(); }
    float rs = rsqrtf(red[0] / D_ + 1e-5f);
    __syncthreads();
    for (int d = tid; d < D_; d += 256)
        p[d] = (p[d] - mu) * rs * ln_g[d] + ln_b[d];
    __syncthreads();
    int w = tid >> 5, lane = tid & 31;
    float acc = 0.f;
    for (int d = lane; d < D_; d += 32) acc += p[d] * cls_W[d*C_ + w];
#pragma unroll
    for (int o = 16; o > 0; o >>= 1) acc += __shfl_down_sync(0xffffffffu, acc, o);
    if (lane == 0) {
        float v = acc + cls_b[w];
        if (!isfinite(v)) v = 0.f;
        out[b*C_ + w] = v;
    }
}

// ---------------- launch -----------------------------------------------------
extern "C" void kernel_launch(void* const* d_in, const int* in_sizes, int n_in,
                              void* d_out, int out_size)
{
    const int*   ids  = (const int*)  d_in[0];
    const int*   mask = (const int*)  d_in[1];
    const float* tok  = (const float*)d_in[2];
    const float* pos  = (const float*)d_in[3];
    const float* Wq   = (const float*)d_in[4];
    const float* Wk   = (const float*)d_in[5];
    const float* Wv   = (const float*)d_in[6];
    const float* gW   = (const float*)d_in[7];
    const float* gb   = (const float*)d_in[8];
    const float* lng  = (const float*)d_in[9];
    const float* lnb  = (const float*)d_in[10];
    const float* cW   = (const float*)d_in[11];
    const float* cb   = (const float*)d_in[12];
    const float* mem  = (const float*)d_in[13];
    float* out = (float*)d_out;

    float *px, *pQV, *pM0, *pM1, *pMt0, *pMt1, *pW, *pWp, *pgWr, *pcwp;
    cudaGetSymbolAddress((void**)&px,   g_x);
    cudaGetSymbolAddress((void**)&pQV,  g_QV);
    cudaGetSymbolAddress((void**)&pM0,  g_M0);
    cudaGetSymbolAddress((void**)&pM1,  g_M1);
    cudaGetSymbolAddress((void**)&pMt0, g_Mt0);
    cudaGetSymbolAddress((void**)&pMt1, g_Mt1);
    cudaGetSymbolAddress((void**)&pW,   g_W);
    cudaGetSymbolAddress((void**)&pWp,  g_Wp);
    cudaGetSymbolAddress((void**)&pgWr, g_gWr);
    cudaGetSymbolAddress((void**)&pcwp, g_cwp);

    auto kWqk = gemm_tc<128,128,64,32, 1, true , true , 3>;  // Wqk = Wq @ Wk^T
    auto kBig = gemm_tc<128,128,64,32, 0, false, false, 3>;  // QV = x @ [Wqk|Wv]

    const int SM_WQK = 3*(128*36 + 128*36)*4;  // 110592
    const int SM_BIG = 3*(128*36 +  32*136)*4; // 107520
    const int SM_SCO = SCO_NST*2*(64*36)*4;    // 73728
    const int SM_GW  = GW_NST*(2304 + 4352)*4; // 79872

    cudaFuncSetAttribute(kWqk, cudaFuncAttributeMaxDynamicSharedMemorySize, SM_WQK);
    cudaFuncSetAttribute(kBig, cudaFuncAttributeMaxDynamicSharedMemorySize, SM_BIG);
    cudaFuncSetAttribute(k_score_softmax, cudaFuncAttributeMaxDynamicSharedMemorySize, SM_SCO);
    cudaFuncSetAttribute(k_gatewrite,     cudaFuncAttributeMaxDynamicSharedMemorySize, SM_GW);

    k_embed<<<B_*T_, 192>>>(ids, tok, pos);
    kWqk<<<dim3(D_/128, D_/128, 1), 256, SM_WQK>>>(Wq, Wk, pWp, D_, D_, D_, D_, D_, NW_);
    k_setup<<<NB_MINIT + NB_PREP + B_, 256>>>(mem, gW, Wv, mask);
    kBig<<<dim3(NW_/128, (B_*T_)/128, 1), 256, SM_BIG>>>(px, pWp, pQV, B_*T_, NW_, D_, D_, NW_, NW_);

    float* Mbuf [2] = {pM0,  pM1};
    float* Mtbuf[2] = {pMt0, pMt1};
    for (int step = 0; step < 4; step++) {
        const float* Mc  = Mbuf [step & 1];
        const float* Mtc = Mtbuf[step & 1];
        float*       Mn  = Mbuf [(step & 1) ^ 1];
        float*       Mtn = Mtbuf[(step & 1) ^ 1];
        k_score_softmax<<<dim3(1, T_/64, B_), 128, SM_SCO>>>(pQV, Mtc, pW, mask, nullptr);
        k_gatewrite<<<dim3(D_/128, 1, B_), 256, SM_GW>>>(Mc, Mtc, pgWr, pW, pQV, gb, Mn, Mtn);
    }
    // after 4 steps state is back in M0/Mt0; final read -> colsum partials only
    k_score_softmax<<<dim3(1, T_/64, B_), 128, SM_SCO>>>(pQV, pMt0, nullptr, mask, pcwp);
    k_final<<<B_, 256>>>(lng, lnb, cW, cb, out);
}